// round 1
// baseline (speedup 1.0000x reference)
#include <cuda_runtime.h>

#define T_STEPS 2000
#define N_IN    8192
#define N_OUT   4096

// 32 MB scratch for lif_input = x @ W^T  (allocation-free: __device__ global)
__device__ float g_lif[(size_t)T_STEPS * N_OUT];

// ---------------------------------------------------------------------------
// Phase 1: fp32 GEMM  C[M,N] = A[M,K] * B[N,K]^T  (both operands K-contiguous)
// 128x128 block tile, BK=8, 256 threads, 8x8 register micro-tile per thread.
// ---------------------------------------------------------------------------
constexpr int BM = 128, BN = 128, BK = 8, TM = 8, TN = 8;

__global__ __launch_bounds__(256, 2)
void gemm_nt_kernel(const float* __restrict__ A,   // [M,K]
                    const float* __restrict__ B,   // [N,K]
                    float* __restrict__ C,         // [M,N]
                    int M, int N, int K)
{
    __shared__ float As[BK][BM];
    __shared__ float Bs[BK][BN];

    const int tid = threadIdx.x;
    const int bm  = blockIdx.y * BM;
    const int bn  = blockIdx.x * BN;

    // Each thread loads one float4 of A and one of B per BK-slab:
    // 128 rows x 8 k -> 256 float4 loads, 256 threads.
    const int loadRow = tid >> 1;         // 0..127
    const int loadCol = (tid & 1) * 4;    // 0 or 4

    // 16x16 thread grid, each owns an 8x8 tile of C.
    const int tr = (tid >> 4) * TM;       // 0..120
    const int tc = (tid & 15) * TN;       // 0..120

    float acc[TM][TN];
    #pragma unroll
    for (int i = 0; i < TM; i++)
        #pragma unroll
        for (int j = 0; j < TN; j++)
            acc[i][j] = 0.0f;

    const bool aValid = (bm + loadRow) < M;   // M=2000 boundary (N,K exact)
    const float* Aptr = A + (size_t)(bm + loadRow) * K + loadCol;
    const float* Bptr = B + (size_t)(bn + loadRow) * K + loadCol;

    for (int k0 = 0; k0 < K; k0 += BK) {
        float4 a4 = aValid ? *(const float4*)(Aptr + k0)
                           : make_float4(0.f, 0.f, 0.f, 0.f);
        float4 b4 = *(const float4*)(Bptr + k0);

        As[loadCol + 0][loadRow] = a4.x;
        As[loadCol + 1][loadRow] = a4.y;
        As[loadCol + 2][loadRow] = a4.z;
        As[loadCol + 3][loadRow] = a4.w;
        Bs[loadCol + 0][loadRow] = b4.x;
        Bs[loadCol + 1][loadRow] = b4.y;
        Bs[loadCol + 2][loadRow] = b4.z;
        Bs[loadCol + 3][loadRow] = b4.w;
        __syncthreads();

        #pragma unroll
        for (int k = 0; k < BK; k++) {
            float ar[TM], br[TN];
            #pragma unroll
            for (int i = 0; i < TM; i++) ar[i] = As[k][tr + i];
            #pragma unroll
            for (int j = 0; j < TN; j++) br[j] = Bs[k][tc + j];
            #pragma unroll
            for (int i = 0; i < TM; i++)
                #pragma unroll
                for (int j = 0; j < TN; j++)
                    acc[i][j] += ar[i] * br[j];
        }
        __syncthreads();
    }

    #pragma unroll
    for (int i = 0; i < TM; i++) {
        int gm = bm + tr + i;
        if (gm < M) {
            float* Crow = C + (size_t)gm * N + bn + tc;
            #pragma unroll
            for (int j = 0; j < TN; j += 4) {
                float4 v = make_float4(acc[i][j], acc[i][j+1],
                                       acc[i][j+2], acc[i][j+3]);
                *(float4*)(Crow + j) = v;
            }
        }
    }
}

// ---------------------------------------------------------------------------
// Phase 2: sequential LIF scan. One thread per output neuron; loads of
// lif_input are coalesced across the warp (N_OUT contiguous).
// Op order mirrors the reference exactly:
//   leak -> gated integrate -> refrac countdown -> spike -> reset
// ---------------------------------------------------------------------------
__global__ __launch_bounds__(256)
void lif_scan_kernel(const float* __restrict__ lif,
                     float* __restrict__ out,
                     const float* __restrict__ v_th,
                     const float* __restrict__ v_rest,
                     const float* __restrict__ v_reset,
                     const float* __restrict__ t_ref,
                     const float* __restrict__ tau)
{
    const int n = blockIdx.x * blockDim.x + threadIdx.x;
    if (n >= N_OUT) return;

    const float DT   = 0.001f;
    const float th   = v_th[n];
    const float rest = v_rest[n];
    const float rst  = v_reset[n];
    const float trf  = t_ref[n];
    const float dt_tau = DT * tau[n];   // matches (DT*tau)*(v-v_rest) ordering

    float v      = rest;   // v[0] = v_rest
    float refrac = 0.0f;

    out[n] = 0.0f;         // s[0] = 0 (d_out is poisoned, must init)

    for (int t = 1; t < T_STEPS; t++) {
        float inp = lif[(size_t)t * N_OUT + n];
        // leak toward v_rest
        v = v - dt_tau * (v - rest);
        // integrate only when not refractory (refrac from previous step)
        if (refrac == 0.0f) v += inp;
        // count down refractory period
        refrac = (refrac > 0.0f) ? (refrac - DT) : 0.0f;
        // heavyside spike
        float spike = (v - th >= 0.0f) ? 1.0f : 0.0f;
        // reset
        if (spike > 0.0f) { refrac = trf; v = rst; }
        out[(size_t)t * N_OUT + n] = spike;
    }
}

// ---------------------------------------------------------------------------
extern "C" void kernel_launch(void* const* d_in, const int* in_sizes, int n_in,
                              void* d_out, int out_size)
{
    const float* x       = (const float*)d_in[0];  // [T, N_IN]
    const float* weight  = (const float*)d_in[1];  // [N_OUT, N_IN]
    const float* v_th    = (const float*)d_in[2];
    const float* v_rest  = (const float*)d_in[3];
    const float* v_reset = (const float*)d_in[4];
    const float* t_ref   = (const float*)d_in[5];
    const float* tau     = (const float*)d_in[6];
    float* out = (float*)d_out;                    // [T, N_OUT]

    float* lif_ptr = nullptr;
    cudaGetSymbolAddress((void**)&lif_ptr, g_lif);

    // GEMM: M=2000, N=4096, K=8192
    dim3 grid(N_OUT / BN, (T_STEPS + BM - 1) / BM);
    gemm_nt_kernel<<<grid, 256>>>(x, weight, lif_ptr, T_STEPS, N_OUT, N_IN);

    // Scan: one thread per neuron
    lif_scan_kernel<<<N_OUT / 256, 256>>>(lif_ptr, out,
                                          v_th, v_rest, v_reset, t_ref, tau);
}